// round 7
// baseline (speedup 1.0000x reference)
#include <cuda_runtime.h>
#include <cstdint>

// EngramGating: B=16, S=16384, DIM=32, H=4  (T = 262144 tokens)
// out[t,h,k] = sigmoid(signed_sqrt(gate_raw[t,h])) * (emb[t] @ Wv^T + bv)[k]
// gate_raw[t,h] = sum_k( rms(key)*g1 * rms(q)*g2 ) / sqrt(32)
// key[t,h,k] = sum_d emb[t,d] * Wk[h,k,d] + bk[h,k]
//
// R7: software pipeline. q double-buffered via cp.async (wait deferred to
// epilogue); emb register-prefetched one iteration ahead. Wk swizzle
// (k ^ 2*(k>>4&1) ^ h, stride 512) -> smem exactly 56KB/block, 4 blocks/SM.

#define DIM 32
#define HC  4
#define TTOK 8
#define WARPS_PER_BLOCK 4
#define THREADS (WARPS_PER_BLOCK * 32)
#define GRID_BLOCKS 592            // 148 SMs * 4 blocks -> one wave

// dynamic smem layout (bytes)
#define SWK_BYTES  (HC * 512 * 8)                        // 16384
#define SWV_BYTES  (16 * 32 * 8)                         //  4096
#define SE_BYTES   (WARPS_PER_BLOCK * TTOK * DIM * 4)    //  4096
#define SQ_BYTES   (WARPS_PER_BLOCK * 2 * TTOK * HC * DIM * 4)  // 32768
#define SMEM_TOTAL (SWK_BYTES + SWV_BYTES + SE_BYTES + SQ_BYTES) // 57344

__device__ __forceinline__ void fma2(unsigned long long& acc,
                                     unsigned long long a,
                                     unsigned long long b) {
    asm("fma.rn.f32x2 %0, %1, %2, %0;" : "+l"(acc) : "l"(a), "l"(b));
}

__device__ __forceinline__ float hadd2(unsigned long long v) {
    return __uint_as_float((unsigned)v) + __uint_as_float((unsigned)(v >> 32));
}

__device__ __forceinline__ unsigned smem_u32(const void* p) {
    return (unsigned)__cvta_generic_to_shared(p);
}

__device__ __forceinline__ void cp_async16(unsigned saddr, const void* gptr) {
    asm volatile("cp.async.cg.shared.global [%0], [%1], 16;"
                 :: "r"(saddr), "l"(gptr));
}
#define CP_COMMIT()  asm volatile("cp.async.commit_group;")
#define CP_WAIT1()   asm volatile("cp.async.wait_group 1;")

__global__ void __launch_bounds__(THREADS, 4)
engram_gating_kernel(const float* __restrict__ emb,      // [T,32]
                     const float* __restrict__ hid,      // [T,4,32]
                     const float* __restrict__ Wv,       // [32,32]
                     const float* __restrict__ bv,       // [32]
                     const float* __restrict__ Wk,       // [4,32,32]
                     const float* __restrict__ bk,       // [4,32]
                     const float* __restrict__ g1,       // [4,32]
                     const float* __restrict__ g2,       // [4,32]
                     float* __restrict__ out,            // [T,4,32]
                     int nTok) {
    extern __shared__ char smem_raw[];
    unsigned long long* sWk = (unsigned long long*)smem_raw;
    unsigned long long* sWv = (unsigned long long*)(smem_raw + SWK_BYTES);
    float* sE = (float*)(smem_raw + SWK_BYTES + SWV_BYTES);
    float* sQ = (float*)(smem_raw + SWK_BYTES + SWV_BYTES + SE_BYTES);

    const int tid = threadIdx.x;

    // ---- stage weights (once per block) ----
    {
        // Wk element (h,k,d): u64 index gI covers d-pair dp of row (h,k)
        const unsigned long long* WkU = (const unsigned long long*)Wk;
        for (int gI = tid; gI < HC * 32 * 16; gI += THREADS) {
            int h = gI >> 9, k = (gI >> 4) & 31, dp = gI & 15;
            int slot = k ^ (2 * ((k >> 4) & 1)) ^ h;   // conflict-free swizzle
            sWk[h * 512 + dp * 32 + slot] = WkU[gI];
        }
        const unsigned long long* WvU = (const unsigned long long*)Wv;
        for (int gI = tid; gI < 32 * 16; gI += THREADS) {
            int k = gI >> 4, dp = gI & 15;
            sWv[dp * 32 + k] = WvU[gI];
        }
    }
    __syncthreads();

    const int lane = tid & 31;
    const int w = tid >> 5;
    const int hH = lane >> 3;          // head of this lane
    const int iI = lane & 7;           // index within 8-lane group
    const int sSw = 2 * (iI >> 2);

    // ---- per-lane constants ----
    float bkc[4], ggc[4];
#pragma unroll
    for (int c = 0; c < 4; c++) {
        int k = 4 * iI + c;
        bkc[c] = bk[hH * DIM + k];
        ggc[c] = g1[hH * DIM + k] * g2[hH * DIM + k];
    }
    const float bvl = bv[lane];
    int wkoff[4];
#pragma unroll
    for (int c = 0; c < 4; c++)
        wkoff[c] = hH * 512 + (((4 * iI + c) ^ sSw) ^ hH);

    float* sEw = sE + w * (TTOK * DIM);                   // 1 KB / warp
    float* sQw = sQ + w * (2 * TTOK * HC * DIM);          // 2 stages x 4 KB
    const unsigned sQaddr0 = smem_u32(sQw);
    const unsigned sQaddr1 = smem_u32(sQw + TTOK * HC * DIM);

    const int warpG = blockIdx.x * WARPS_PER_BLOCK + w;
    const int nWarps = gridDim.x * WARPS_PER_BLOCK;
    const int nGroups = (nTok + TTOK - 1) / TTOK;

    const float EPS = 1.1920929e-07f;
    const float INV32 = 0.03125f;
    const float INVSQRT32 = 0.17677669529663687f;

    // ---- helpers (lambdas keep register scopes tight) ----
    auto issue_q = [&](int g, unsigned saddr) {
        const int tb = g * TTOK;
        if ((tb + TTOK) <= nTok) {
            const char* hp = (const char*)(hid + (size_t)tb * (HC * DIM));
#pragma unroll
            for (int t = 0; t < TTOK; t++)
                cp_async16(saddr + t * 512 + lane * 16, hp + t * 512 + lane * 16);
        } else {
            // rare tail: synchronous scalar fill
            float* dst = (w == w) ? nullptr : nullptr;
            (void)dst;
            float* sdst = sQw + ((saddr == sQaddr0) ? 0 : TTOK * HC * DIM);
            for (int t = 0; t < TTOK; t++) {
                int tok = tb + t;
                for (int r = 0; r < 4; r++)
                    sdst[t * 128 + r * 32 + lane] =
                        (tok < nTok) ? hid[(size_t)tok * 128 + r * 32 + lane] : 0.f;
            }
        }
    };
    auto load_emb = [&](int g, float4& e0, float4& e1) {
        const int tb = g * TTOK;
        if ((tb + TTOK) <= nTok) {
            const float4* ep = (const float4*)(emb + (size_t)tb * DIM);
            e0 = ep[lane];
            e1 = ep[32 + lane];
        } else {
            float v[8];
            int lim = nTok * DIM;
            for (int r = 0; r < 8; r++) {
                int fi = tb * DIM + ((r < 4) ? lane * 4 + r : 128 + lane * 4 + (r - 4));
                v[r] = (fi < lim) ? emb[fi] : 0.f;
            }
            e0 = make_float4(v[0], v[1], v[2], v[3]);
            e1 = make_float4(v[4], v[5], v[6], v[7]);
        }
    };

    // ---- pipeline prologue ----
    float4 e0, e1;
    int stage = 0;
    if (warpG < nGroups) {
        load_emb(warpG, e0, e1);
        issue_q(warpG, sQaddr0);
    }
    CP_COMMIT();

    for (int g = warpG; g < nGroups; g += nWarps) {
        const int tb = g * TTOK;
        const bool full = (tb + TTOK) <= nTok;
        const int gn = g + nWarps;
        const unsigned sQcur = stage ? sQaddr1 : sQaddr0;
        const unsigned sQnxt = stage ? sQaddr0 : sQaddr1;

        // ---- issue NEXT group's q (other stage); always commit one group ----
        if (gn < nGroups) issue_q(gn, sQnxt);
        CP_COMMIT();

        // ---- publish current emb to smem; prefetch next emb into regs ----
        *(float4*)&sEw[lane * 4] = e0;
        *(float4*)&sEw[128 + lane * 4] = e1;
        if (gn < nGroups) load_emb(gn, e0, e1);
        __syncwarp();

        // ---- mat-vec: 4 keys + value, 8 tokens, d-pair packed FMA2 ----
        unsigned long long acck[TTOK][4];
        unsigned long long accv[TTOK];
#pragma unroll
        for (int t = 0; t < TTOK; t++) {
            accv[t] = 0ull;
#pragma unroll
            for (int c = 0; c < 4; c++) acck[t][c] = 0ull;
        }

        const unsigned long long* eP = (const unsigned long long*)sEw;
#pragma unroll
        for (int dp = 0; dp < 16; dp++) {
            unsigned long long wv  = sWv[dp * 32 + lane];
            unsigned long long wk0 = sWk[wkoff[0] + dp * 32];
            unsigned long long wk1 = sWk[wkoff[1] + dp * 32];
            unsigned long long wk2 = sWk[wkoff[2] + dp * 32];
            unsigned long long wk3 = sWk[wkoff[3] + dp * 32];
#pragma unroll
            for (int t = 0; t < TTOK; t++) {
                unsigned long long e2 = eP[t * 16 + dp];   // broadcast LDS.64
                fma2(accv[t], wv, e2);
                fma2(acck[t][0], wk0, e2);
                fma2(acck[t][1], wk1, e2);
                fma2(acck[t][2], wk2, e2);
                fma2(acck[t][3], wk3, e2);
            }
        }

        // ---- current q guaranteed done when <=1 group (the next) pending ----
        CP_WAIT1();
        __syncwarp();

        const float* qB = (const float*)(sQw + (stage ? TTOK * HC * DIM : 0));

        // ---- epilogue per token ----
#pragma unroll
        for (int t = 0; t < TTOK; t++) {
            int tok = tb + t;
            if (full || tok < nTok) {
                float k0 = hadd2(acck[t][0]) + bkc[0];
                float k1 = hadd2(acck[t][1]) + bkc[1];
                float k2 = hadd2(acck[t][2]) + bkc[2];
                float k3 = hadd2(acck[t][3]) + bkc[3];
                float4 q = *(const float4*)&qB[t * 128 + lane * 4];

                float kk = k0 * k0 + k1 * k1 + k2 * k2 + k3 * k3;
                float qq = q.x * q.x + q.y * q.y + q.z * q.z + q.w * q.w;
                float kq = k0 * ggc[0] * q.x + k1 * ggc[1] * q.y
                         + k2 * ggc[2] * q.z + k3 * ggc[3] * q.w;

                // 3-step butterfly in 8-lane groups (serves 4 heads/instr)
#pragma unroll
                for (int m = 1; m < 8; m <<= 1) {
                    kk += __shfl_xor_sync(0xffffffffu, kk, m);
                    qq += __shfl_xor_sync(0xffffffffu, qq, m);
                    kq += __shfl_xor_sync(0xffffffffu, kq, m);
                }

                float r = kq * rsqrtf(fmaf(kk, INV32, EPS))
                             * rsqrtf(fmaf(qq, INV32, EPS)) * INVSQRT32;
                float a = sqrtf(fmaxf(fabsf(r), 1e-6f));
                a = (r > 0.f) ? a : ((r < 0.f) ? -a : 0.f);
                float gate = 1.0f / (1.0f + __expf(-a));

                // value (lane=k mapping) -> this lane's 4 k's of its head
                float val = hadd2(accv[t]) + bvl;
                float v0 = __shfl_sync(0xffffffffu, val, 4 * iI + 0);
                float v1 = __shfl_sync(0xffffffffu, val, 4 * iI + 1);
                float v2 = __shfl_sync(0xffffffffu, val, 4 * iI + 2);
                float v3 = __shfl_sync(0xffffffffu, val, 4 * iI + 3);

                float4 o = make_float4(gate * v0, gate * v1, gate * v2, gate * v3);
                *(float4*)(out + (size_t)tok * (HC * DIM) + lane * 4) = o;
            }
        }
        __syncwarp();     // protect sE (reg-publish) before next iteration
        stage ^= 1;
    }
}

extern "C" void kernel_launch(void* const* d_in, const int* in_sizes, int n_in,
                              void* d_out, int out_size) {
    const float* emb = (const float*)d_in[0];
    const float* hid = (const float*)d_in[1];
    const float* Wv  = (const float*)d_in[2];
    const float* bv  = (const float*)d_in[3];
    const float* Wk  = (const float*)d_in[4];
    const float* bk  = (const float*)d_in[5];
    const float* g1  = (const float*)d_in[6];
    const float* g2  = (const float*)d_in[7];
    float* out = (float*)d_out;

    int nTok = in_sizes[0] / DIM;

    static bool attr_set = false;   // idempotent attribute set (host-side, capture-safe)
    cudaFuncSetAttribute(engram_gating_kernel,
                         cudaFuncAttributeMaxDynamicSharedMemorySize, SMEM_TOTAL);
    (void)attr_set;

    engram_gating_kernel<<<GRID_BLOCKS, THREADS, SMEM_TOTAL>>>(
        emb, hid, Wv, bv, Wk, bk, g1, g2, out, nTok);
}